// round 2
// baseline (speedup 1.0000x reference)
#include <cuda_runtime.h>
#include <cuda_bf16.h>
#include <math.h>

// Problem constants
#define BATCH 4
#define SEQ   2048
#define EMB   1024
#define NH    16
#define HD    64
#define M_ROWS (BATCH * SEQ)      // 8192

// ---------------- scratch (no allocations allowed; referenced directly from device code) ----
__device__ float g_q[M_ROWS * EMB];
__device__ float g_k[M_ROWS * EMB];
__device__ float g_v[M_ROWS * EMB];
__device__ float g_attn[M_ROWS * EMB];

// ---------------- SGEMM: C[m][n] = alpha * sum_k X[m][k] * W[n][k] (+bias[n]) ----
// X: (M, K) row-major. W: (N, K) row-major (torch Linear weight layout).
// dst selector: 0 -> g_q, 1 -> g_k, 2 -> g_v, 3 -> C argument (d_out)
// src selector: 0 -> X argument, 1 -> g_attn
#define BM 128
#define BN 128
#define BK 8
#define TM 8
#define TN 8

__global__ __launch_bounds__(256) void sgemm_xwT(
    const float* __restrict__ Xarg, const float* __restrict__ W,
    const float* __restrict__ bias, float* __restrict__ Carg,
    int M, int N, int K, float alpha, int src, int dst)
{
    const float* X = (src == 0) ? Xarg : g_attn;
    float* C;
    switch (dst) {
        case 0: C = g_q; break;
        case 1: C = g_k; break;
        case 2: C = g_v; break;
        default: C = Carg; break;
    }

    __shared__ float As[BK][BM];
    __shared__ float Bs[BK][BN];

    const int tid = threadIdx.x;
    const int tx = tid & 15;
    const int ty = tid >> 4;
    const int row0 = blockIdx.y * BM;
    const int col0 = blockIdx.x * BN;

    const int lr = tid >> 1;            // 0..127
    const int lc = (tid & 1) * 4;       // 0 or 4

    float acc[TM][TN];
#pragma unroll
    for (int i = 0; i < TM; i++)
#pragma unroll
        for (int j = 0; j < TN; j++) acc[i][j] = 0.0f;

    for (int k0 = 0; k0 < K; k0 += BK) {
        float4 xv = *(const float4*)(X + (size_t)(row0 + lr) * K + k0 + lc);
        As[lc + 0][lr] = xv.x;
        As[lc + 1][lr] = xv.y;
        As[lc + 2][lr] = xv.z;
        As[lc + 3][lr] = xv.w;
        float4 wv = *(const float4*)(W + (size_t)(col0 + lr) * K + k0 + lc);
        Bs[lc + 0][lr] = wv.x;
        Bs[lc + 1][lr] = wv.y;
        Bs[lc + 2][lr] = wv.z;
        Bs[lc + 3][lr] = wv.w;
        __syncthreads();

#pragma unroll
        for (int kk = 0; kk < BK; kk++) {
            float a[TM], b[TN];
#pragma unroll
            for (int i = 0; i < TM; i++) a[i] = As[kk][ty * TM + i];
#pragma unroll
            for (int j = 0; j < TN; j++) b[j] = Bs[kk][tx * TN + j];
#pragma unroll
            for (int i = 0; i < TM; i++)
#pragma unroll
                for (int j = 0; j < TN; j++)
                    acc[i][j] = fmaf(a[i], b[j], acc[i][j]);
        }
        __syncthreads();
    }

#pragma unroll
    for (int i = 0; i < TM; i++) {
        const int r = row0 + ty * TM + i;
#pragma unroll
        for (int j = 0; j < TN; j++) {
            const int c = col0 + tx * TN + j;
            float v = acc[i][j] * alpha;
            if (bias) v += bias[c];
            C[(size_t)r * N + c] = v;
        }
    }
}

// ---------------- Flash attention (fp32, online softmax) ----------------
// Reads g_q / g_k / g_v, writes g_attn. All in (B, L, E) layout; head h is
// columns [h*HD, h*HD+HD). Q pre-scaled by HD^-0.5 (folded into Q projection).
#define BQ  64
#define BKV 32

__global__ __launch_bounds__(256) void flash_attn()
{
    __shared__ float Qs[BQ][HD + 1];
    __shared__ float Ks[BKV][HD + 1];
    __shared__ float Vs[BKV][HD + 1];
    __shared__ float Ss[BQ][BKV + 1];

    const int tid = threadIdx.x;
    const int tx = tid & 15;
    const int ty = tid >> 4;
    const int bh = blockIdx.y;
    const int b = bh >> 4;
    const int h = bh & 15;
    const int q0 = blockIdx.x * BQ;

    const size_t base = ((size_t)b * SEQ) * EMB + (size_t)h * HD;

    for (int i = tid; i < BQ * HD; i += 256) {
        const int r = i >> 6, c = i & 63;
        Qs[r][c] = g_q[base + (size_t)(q0 + r) * EMB + c];
    }

    float o[4][4];
    float m_i[4], l_i[4];
#pragma unroll
    for (int i = 0; i < 4; i++) {
        m_i[i] = -1e30f;
        l_i[i] = 0.0f;
#pragma unroll
        for (int j = 0; j < 4; j++) o[i][j] = 0.0f;
    }
    __syncthreads();

    for (int s0 = 0; s0 < SEQ; s0 += BKV) {
        for (int i = tid; i < BKV * HD; i += 256) {
            const int r = i >> 6, c = i & 63;
            Ks[r][c] = g_k[base + (size_t)(s0 + r) * EMB + c];
            Vs[r][c] = g_v[base + (size_t)(s0 + r) * EMB + c];
        }
        __syncthreads();

        // S = Q K^T : 4 rows x 2 cols per thread
        float s[4][2];
#pragma unroll
        for (int i = 0; i < 4; i++) { s[i][0] = 0.0f; s[i][1] = 0.0f; }
#pragma unroll
        for (int d = 0; d < HD; d++) {
            float a[4], bb[2];
#pragma unroll
            for (int i = 0; i < 4; i++) a[i] = Qs[ty * 4 + i][d];
            bb[0] = Ks[tx * 2 + 0][d];
            bb[1] = Ks[tx * 2 + 1][d];
#pragma unroll
            for (int i = 0; i < 4; i++) {
                s[i][0] = fmaf(a[i], bb[0], s[i][0]);
                s[i][1] = fmaf(a[i], bb[1], s[i][1]);
            }
        }

        // row max across the 16 tx lanes (xor offsets stay inside half-warp)
        float mt[4];
#pragma unroll
        for (int i = 0; i < 4; i++) {
            mt[i] = fmaxf(s[i][0], s[i][1]);
#pragma unroll
            for (int off = 8; off > 0; off >>= 1)
                mt[i] = fmaxf(mt[i], __shfl_xor_sync(0xffffffffu, mt[i], off));
        }

        float corr[4];
#pragma unroll
        for (int i = 0; i < 4; i++) {
            const float mn = fmaxf(m_i[i], mt[i]);
            corr[i] = __expf(m_i[i] - mn);
            m_i[i] = mn;
        }

        float ssum[4];
#pragma unroll
        for (int i = 0; i < 4; i++) {
            const float p0 = __expf(s[i][0] - m_i[i]);
            const float p1 = __expf(s[i][1] - m_i[i]);
            Ss[ty * 4 + i][tx * 2 + 0] = p0;
            Ss[ty * 4 + i][tx * 2 + 1] = p1;
            ssum[i] = p0 + p1;
#pragma unroll
            for (int off = 8; off > 0; off >>= 1)
                ssum[i] += __shfl_xor_sync(0xffffffffu, ssum[i], off);
            l_i[i] = l_i[i] * corr[i] + ssum[i];
        }

#pragma unroll
        for (int i = 0; i < 4; i++)
#pragma unroll
            for (int j = 0; j < 4; j++) o[i][j] *= corr[i];

        __syncthreads();   // Ss fully written

        // O += P @ V : 4 rows x 4 dims per thread
#pragma unroll
        for (int kc = 0; kc < BKV; kc++) {
            float a[4], bb[4];
#pragma unroll
            for (int i = 0; i < 4; i++) a[i] = Ss[ty * 4 + i][kc];
#pragma unroll
            for (int j = 0; j < 4; j++) bb[j] = Vs[kc][tx * 4 + j];
#pragma unroll
            for (int i = 0; i < 4; i++)
#pragma unroll
                for (int j = 0; j < 4; j++)
                    o[i][j] = fmaf(a[i], bb[j], o[i][j]);
        }
        __syncthreads();   // done reading Ks/Vs/Ss for this tile
    }

#pragma unroll
    for (int i = 0; i < 4; i++) {
        const float inv = 1.0f / l_i[i];
        const size_t rowoff = base + (size_t)(q0 + ty * 4 + i) * EMB;
#pragma unroll
        for (int j = 0; j < 4; j++)
            g_attn[rowoff + tx * 4 + j] = o[i][j] * inv;
    }
}

// ---------------- launch (pure kernel launches; graph-capture safe) ----------------
extern "C" void kernel_launch(void* const* d_in, const int* in_sizes, int n_in,
                              void* d_out, int out_size)
{
    const float* query = (const float*)d_in[0];
    const float* key   = (const float*)d_in[1];
    const float* value = (const float*)d_in[2];
    const float* w_in  = (const float*)d_in[3];   // (3E, E)
    const float* w_out = (const float*)d_in[4];   // (E, E)
    const float* b_out = (const float*)d_in[5];   // (E,)
    float* out = (float*)d_out;

    dim3 gemm_grid(EMB / BN, M_ROWS / BM);   // (8, 64)
    const float sm_scale = 0.125f;           // HD^-0.5, folded into Q projection

    // QKV projections (outputs selected by dst: 0=g_q, 1=g_k, 2=g_v)
    sgemm_xwT<<<gemm_grid, 256>>>(query, w_in,               nullptr, nullptr,
                                  M_ROWS, EMB, EMB, sm_scale, 0, 0);
    sgemm_xwT<<<gemm_grid, 256>>>(key,   w_in + 1024 * 1024, nullptr, nullptr,
                                  M_ROWS, EMB, EMB, 1.0f,     0, 1);
    sgemm_xwT<<<gemm_grid, 256>>>(value, w_in + 2048 * 1024, nullptr, nullptr,
                                  M_ROWS, EMB, EMB, 1.0f,     0, 2);

    // attention: g_q,g_k,g_v -> g_attn
    dim3 fa_grid(SEQ / BQ, BATCH * NH);      // (32, 64)
    flash_attn<<<fa_grid, 256>>>();

    // output projection + bias: g_attn -> d_out
    sgemm_xwT<<<gemm_grid, 256>>>(nullptr, w_out, b_out, out,
                                  M_ROWS, EMB, EMB, 1.0f, 1, 3);
}

// round 3
// speedup vs baseline: 3.2582x; 3.2582x over previous
#include <cuda_runtime.h>
#include <cuda_bf16.h>
#include <math.h>
#include <stdint.h>

// Problem constants
#define BATCH 4
#define SEQ   2048
#define EMB   1024
#define NH    16
#define HD    64
#define M_ROWS (BATCH * SEQ)      // 8192

// ---------------- scratch (no allocations allowed) ----------------
__device__ float g_q[M_ROWS * EMB];
__device__ float g_k[M_ROWS * EMB];
__device__ float g_v[M_ROWS * EMB];
__device__ float g_attn[M_ROWS * EMB];

// ---------------- tf32 mma helpers ----------------
__device__ __forceinline__ uint32_t f2tf(float x) {
    uint32_t r;
    asm("cvt.rna.tf32.f32 %0, %1;" : "=r"(r) : "f"(x));
    return r;
}

__device__ __forceinline__ void mma_tf32(float d[4],
    uint32_t a0, uint32_t a1, uint32_t a2, uint32_t a3,
    uint32_t b0, uint32_t b1)
{
    asm volatile(
        "mma.sync.aligned.m16n8k8.row.col.f32.tf32.tf32.f32 "
        "{%0,%1,%2,%3},{%4,%5,%6,%7},{%8,%9},{%0,%1,%2,%3};"
        : "+f"(d[0]), "+f"(d[1]), "+f"(d[2]), "+f"(d[3])
        : "r"(a0), "r"(a1), "r"(a2), "r"(a3), "r"(b0), "r"(b1));
}

// ============================================================================
// GEMM: C[m][n] = alpha * sum_k X[m][k] * W[n][k] (+bias[n])
// tiles 128x128x32, 8 warps (2x4), warp tile 64x32, m16n8k8 tf32 mma,
// cp.async double-buffered SMEM (stride 36 floats -> conflict-free frag loads)
// src: 0 -> Xarg, 1 -> g_attn ; dst: 0 g_q, 1 g_k, 2 g_v, 3 Carg
// ============================================================================
#define GBK 32
#define GST 36
#define GEMM_SMEM_FLOATS (2 * (128 * GST) * 2)   // 2 stages x (Xs + Ws)
#define GEMM_SMEM_BYTES  (GEMM_SMEM_FLOATS * 4)  // 73728

__global__ __launch_bounds__(256, 2) void gemm_tf32(
    const float* __restrict__ Xarg, const float* __restrict__ W,
    const float* __restrict__ bias, float* __restrict__ Carg,
    int M, int N, int K, float alpha, int src, int dst)
{
    extern __shared__ float sm[];
    const float* X = (src == 0) ? Xarg : g_attn;
    float* C;
    switch (dst) {
        case 0: C = g_q; break;
        case 1: C = g_k; break;
        case 2: C = g_v; break;
        default: C = Carg; break;
    }

    const int tid = threadIdx.x;
    const int lane = tid & 31;
    const int w = tid >> 5;
    const int g = lane >> 2;      // groupID
    const int q = lane & 3;       // threadID_in_group
    const int wm = w & 1;         // 2 warps along m
    const int wn = w >> 1;        // 4 warps along n
    const int row0 = blockIdx.y * 128;
    const int col0 = blockIdx.x * 128;

    float acc[4][4][4];
#pragma unroll
    for (int mi = 0; mi < 4; mi++)
#pragma unroll
        for (int nj = 0; nj < 4; nj++)
#pragma unroll
            for (int r = 0; r < 4; r++) acc[mi][nj][r] = 0.0f;

    auto load_stage = [&](int s, int k0) {
        float* Xs = sm + s * (128 * GST * 2);
        float* Ws = Xs + 128 * GST;
#pragma unroll
        for (int i = 0; i < 4; i++) {
            const int f = tid + 256 * i;          // 0..1023
            const int r = f >> 3;
            const int c = (f & 7) * 4;
            uint32_t dX = (uint32_t)__cvta_generic_to_shared(Xs + r * GST + c);
            const float* gX = X + (size_t)(row0 + r) * K + k0 + c;
            asm volatile("cp.async.cg.shared.global [%0],[%1],16;" :: "r"(dX), "l"(gX));
            uint32_t dW = (uint32_t)__cvta_generic_to_shared(Ws + r * GST + c);
            const float* gW = W + (size_t)(col0 + r) * K + k0 + c;
            asm volatile("cp.async.cg.shared.global [%0],[%1],16;" :: "r"(dW), "l"(gW));
        }
        asm volatile("cp.async.commit_group;");
    };

    load_stage(0, 0);
    const int T = K / GBK;       // 32
    for (int t = 0; t < T; t++) {
        if (t + 1 < T) {
            load_stage((t + 1) & 1, (t + 1) * GBK);
            asm volatile("cp.async.wait_group 1;");
        } else {
            asm volatile("cp.async.wait_group 0;");
        }
        __syncthreads();

        const float* Xs = sm + (t & 1) * (128 * GST * 2);
        const float* Ws = Xs + 128 * GST;
#pragma unroll
        for (int kk = 0; kk < 4; kk++) {
            uint32_t a[4][4];
#pragma unroll
            for (int mi = 0; mi < 4; mi++) {
                const int r = wm * 64 + mi * 16 + g;
                a[mi][0] = f2tf(Xs[r * GST + kk * 8 + q]);
                a[mi][1] = f2tf(Xs[(r + 8) * GST + kk * 8 + q]);
                a[mi][2] = f2tf(Xs[r * GST + kk * 8 + q + 4]);
                a[mi][3] = f2tf(Xs[(r + 8) * GST + kk * 8 + q + 4]);
            }
#pragma unroll
            for (int nj = 0; nj < 4; nj++) {
                const int n = wn * 32 + nj * 8 + g;
                uint32_t b0 = f2tf(Ws[n * GST + kk * 8 + q]);
                uint32_t b1 = f2tf(Ws[n * GST + kk * 8 + q + 4]);
#pragma unroll
                for (int mi = 0; mi < 4; mi++)
                    mma_tf32(acc[mi][nj], a[mi][0], a[mi][1], a[mi][2], a[mi][3], b0, b1);
            }
        }
        __syncthreads();
    }

    // epilogue
#pragma unroll
    for (int mi = 0; mi < 4; mi++) {
        const int r1 = row0 + wm * 64 + mi * 16 + g;
#pragma unroll
        for (int nj = 0; nj < 4; nj++) {
            const int c = col0 + wn * 32 + nj * 8 + 2 * q;
            float bf0 = bias ? bias[c] : 0.0f;
            float bf1 = bias ? bias[c + 1] : 0.0f;
            float2 v1 = make_float2(acc[mi][nj][0] * alpha + bf0,
                                    acc[mi][nj][1] * alpha + bf1);
            float2 v2 = make_float2(acc[mi][nj][2] * alpha + bf0,
                                    acc[mi][nj][3] * alpha + bf1);
            *(float2*)(C + (size_t)r1 * N + c) = v1;
            *(float2*)(C + (size_t)(r1 + 8) * N + c) = v2;
        }
    }
}

// ============================================================================
// Flash attention, tf32 tensor cores.
// Block: 128 q-rows x one (b,h); 8 warps, each owns 16 q-rows (full n range ->
// softmax entirely warp-local). KV tiles of 64. P round-trips through
// warp-private SMEM rows. SMEM stride 72 floats -> conflict-free frag loads.
// ============================================================================
#define AST 72
#define ATT_Q_OFF 0
#define ATT_K_OFF (128 * AST)             // 9216
#define ATT_V_OFF (ATT_K_OFF + 64 * AST)  // 13824
#define ATT_P_OFF (ATT_V_OFF + 64 * AST)  // 18432
#define ATT_SMEM_FLOATS (ATT_P_OFF + 128 * AST)  // 27648
#define ATT_SMEM_BYTES (ATT_SMEM_FLOATS * 4)     // 110592

__global__ __launch_bounds__(256, 2) void flash_attn_tf32()
{
    extern __shared__ float sm[];
    float* Qs = sm + ATT_Q_OFF;
    float* Ks = sm + ATT_K_OFF;
    float* Vs = sm + ATT_V_OFF;
    float* Ps = sm + ATT_P_OFF;

    const int tid = threadIdx.x;
    const int lane = tid & 31;
    const int w = tid >> 5;
    const int g = lane >> 2;
    const int q = lane & 3;
    const int bh = blockIdx.y;
    const int b = bh >> 4;
    const int h = bh & 15;
    const int q0 = blockIdx.x * 128;
    const int mbase = w * 16;

    const size_t base = (size_t)b * SEQ * EMB + (size_t)h * HD;

    // load Q tile (128 x 64), converted to tf32 bit patterns
    for (int i = tid; i < 2048; i += 256) {
        const int r = i >> 4;
        const int c = (i & 15) * 4;
        float4 v = *(const float4*)(g_q + base + (size_t)(q0 + r) * EMB + c);
        float* d = Qs + r * AST + c;
        d[0] = __uint_as_float(f2tf(v.x));
        d[1] = __uint_as_float(f2tf(v.y));
        d[2] = __uint_as_float(f2tf(v.z));
        d[3] = __uint_as_float(f2tf(v.w));
    }

    float o[8][4];
#pragma unroll
    for (int nj = 0; nj < 8; nj++)
#pragma unroll
        for (int r = 0; r < 4; r++) o[nj][r] = 0.0f;
    float m1 = -1e30f, m2 = -1e30f, l1 = 0.0f, l2 = 0.0f;

    for (int s0 = 0; s0 < SEQ; s0 += 64) {
        // load K/V tiles (64 x 64 each)
        for (int i = tid; i < 1024; i += 256) {
            const int r = i >> 4;
            const int c = (i & 15) * 4;
            float4 kv = *(const float4*)(g_k + base + (size_t)(s0 + r) * EMB + c);
            float* dk = Ks + r * AST + c;
            dk[0] = __uint_as_float(f2tf(kv.x));
            dk[1] = __uint_as_float(f2tf(kv.y));
            dk[2] = __uint_as_float(f2tf(kv.z));
            dk[3] = __uint_as_float(f2tf(kv.w));
            float4 vv = *(const float4*)(g_v + base + (size_t)(s0 + r) * EMB + c);
            float* dv = Vs + r * AST + c;
            dv[0] = __uint_as_float(f2tf(vv.x));
            dv[1] = __uint_as_float(f2tf(vv.y));
            dv[2] = __uint_as_float(f2tf(vv.z));
            dv[3] = __uint_as_float(f2tf(vv.w));
        }
        __syncthreads();

        // S = Q K^T : per warp 16 x 64 (8 n-frags)
        float s[8][4];
#pragma unroll
        for (int nj = 0; nj < 8; nj++)
#pragma unroll
            for (int r = 0; r < 4; r++) s[nj][r] = 0.0f;

#pragma unroll
        for (int kk = 0; kk < 8; kk++) {
            uint32_t a0 = __float_as_uint(Qs[(mbase + g) * AST + kk * 8 + q]);
            uint32_t a1 = __float_as_uint(Qs[(mbase + g + 8) * AST + kk * 8 + q]);
            uint32_t a2 = __float_as_uint(Qs[(mbase + g) * AST + kk * 8 + q + 4]);
            uint32_t a3 = __float_as_uint(Qs[(mbase + g + 8) * AST + kk * 8 + q + 4]);
#pragma unroll
            for (int nj = 0; nj < 8; nj++) {
                uint32_t b0 = __float_as_uint(Ks[(nj * 8 + g) * AST + kk * 8 + q]);
                uint32_t b1 = __float_as_uint(Ks[(nj * 8 + g) * AST + kk * 8 + q + 4]);
                mma_tf32(s[nj], a0, a1, a2, a3, b0, b1);
            }
        }

        // online softmax (rows r1 = mbase+g, r2 = r1+8; quad = lanes sharing g)
        float mt1 = -1e30f, mt2 = -1e30f;
#pragma unroll
        for (int nj = 0; nj < 8; nj++) {
            mt1 = fmaxf(mt1, fmaxf(s[nj][0], s[nj][1]));
            mt2 = fmaxf(mt2, fmaxf(s[nj][2], s[nj][3]));
        }
        mt1 = fmaxf(mt1, __shfl_xor_sync(0xffffffffu, mt1, 1));
        mt1 = fmaxf(mt1, __shfl_xor_sync(0xffffffffu, mt1, 2));
        mt2 = fmaxf(mt2, __shfl_xor_sync(0xffffffffu, mt2, 1));
        mt2 = fmaxf(mt2, __shfl_xor_sync(0xffffffffu, mt2, 2));

        const float mn1 = fmaxf(m1, mt1);
        const float mn2 = fmaxf(m2, mt2);
        const float corr1 = __expf(m1 - mn1);
        const float corr2 = __expf(m2 - mn2);
        m1 = mn1; m2 = mn2;

        float sum1 = 0.0f, sum2 = 0.0f;
#pragma unroll
        for (int nj = 0; nj < 8; nj++) {
            const float p0 = __expf(s[nj][0] - m1);
            const float p1 = __expf(s[nj][1] - m1);
            const float p2 = __expf(s[nj][2] - m2);
            const float p3 = __expf(s[nj][3] - m2);
            sum1 += p0 + p1;
            sum2 += p2 + p3;
            float* pr1 = Ps + (mbase + g) * AST + nj * 8 + 2 * q;
            pr1[0] = __uint_as_float(f2tf(p0));
            pr1[1] = __uint_as_float(f2tf(p1));
            float* pr2 = Ps + (mbase + g + 8) * AST + nj * 8 + 2 * q;
            pr2[0] = __uint_as_float(f2tf(p2));
            pr2[1] = __uint_as_float(f2tf(p3));
        }
        sum1 += __shfl_xor_sync(0xffffffffu, sum1, 1);
        sum1 += __shfl_xor_sync(0xffffffffu, sum1, 2);
        sum2 += __shfl_xor_sync(0xffffffffu, sum2, 1);
        sum2 += __shfl_xor_sync(0xffffffffu, sum2, 2);
        l1 = l1 * corr1 + sum1;
        l2 = l2 * corr2 + sum2;

#pragma unroll
        for (int nj = 0; nj < 8; nj++) {
            o[nj][0] *= corr1; o[nj][1] *= corr1;
            o[nj][2] *= corr2; o[nj][3] *= corr2;
        }

        __syncwarp();   // Ps rows are warp-private; order writes before reads

        // O += P V : per warp 16 x 64
#pragma unroll
        for (int kk = 0; kk < 8; kk++) {
            uint32_t a0 = __float_as_uint(Ps[(mbase + g) * AST + kk * 8 + q]);
            uint32_t a1 = __float_as_uint(Ps[(mbase + g + 8) * AST + kk * 8 + q]);
            uint32_t a2 = __float_as_uint(Ps[(mbase + g) * AST + kk * 8 + q + 4]);
            uint32_t a3 = __float_as_uint(Ps[(mbase + g + 8) * AST + kk * 8 + q + 4]);
#pragma unroll
            for (int nj = 0; nj < 8; nj++) {
                uint32_t b0 = __float_as_uint(Vs[(kk * 8 + q) * AST + nj * 8 + g]);
                uint32_t b1 = __float_as_uint(Vs[(kk * 8 + q + 4) * AST + nj * 8 + g]);
                mma_tf32(o[nj], a0, a1, a2, a3, b0, b1);
            }
        }
        __syncthreads();   // all warps done with Ks/Vs before next tile load
    }

    // epilogue
    const float inv1 = 1.0f / l1;
    const float inv2 = 1.0f / l2;
#pragma unroll
    for (int nj = 0; nj < 8; nj++) {
        const int c = nj * 8 + 2 * q;
        float2 v1 = make_float2(o[nj][0] * inv1, o[nj][1] * inv1);
        float2 v2 = make_float2(o[nj][2] * inv2, o[nj][3] * inv2);
        *(float2*)(g_attn + base + (size_t)(q0 + mbase + g) * EMB + c) = v1;
        *(float2*)(g_attn + base + (size_t)(q0 + mbase + g + 8) * EMB + c) = v2;
    }
}

// ---------------- launch ----------------
extern "C" void kernel_launch(void* const* d_in, const int* in_sizes, int n_in,
                              void* d_out, int out_size)
{
    const float* query = (const float*)d_in[0];
    const float* key   = (const float*)d_in[1];
    const float* value = (const float*)d_in[2];
    const float* w_in  = (const float*)d_in[3];   // (3E, E)
    const float* w_out = (const float*)d_in[4];   // (E, E)
    const float* b_out = (const float*)d_in[5];   // (E,)
    float* out = (float*)d_out;

    cudaFuncSetAttribute(gemm_tf32, cudaFuncAttributeMaxDynamicSharedMemorySize,
                         GEMM_SMEM_BYTES);
    cudaFuncSetAttribute(flash_attn_tf32, cudaFuncAttributeMaxDynamicSharedMemorySize,
                         ATT_SMEM_BYTES);

    dim3 gemm_grid(EMB / 128, M_ROWS / 128);   // (8, 64)
    const float sm_scale = 0.125f;             // HD^-0.5, folded into Q projection

    gemm_tf32<<<gemm_grid, 256, GEMM_SMEM_BYTES>>>(query, w_in, nullptr, nullptr,
        M_ROWS, EMB, EMB, sm_scale, 0, 0);
    gemm_tf32<<<gemm_grid, 256, GEMM_SMEM_BYTES>>>(key, w_in + 1024 * 1024, nullptr, nullptr,
        M_ROWS, EMB, EMB, 1.0f, 0, 1);
    gemm_tf32<<<gemm_grid, 256, GEMM_SMEM_BYTES>>>(value, w_in + 2048 * 1024, nullptr, nullptr,
        M_ROWS, EMB, EMB, 1.0f, 0, 2);

    dim3 fa_grid(SEQ / 128, BATCH * NH);       // (16, 64)
    flash_attn_tf32<<<fa_grid, 256, ATT_SMEM_BYTES>>>();

    gemm_tf32<<<gemm_grid, 256, GEMM_SMEM_BYTES>>>(nullptr, w_out, b_out, out,
        M_ROWS, EMB, EMB, 1.0f, 1, 3);
}